// round 10
// baseline (speedup 1.0000x reference)
#include <cuda_runtime.h>

#define NNODES 200000
#define NEDGES 3200000
#define HIDF 32
#define SCAN_BS 1024
#define NBLK_SCAN 196           // 196*1024 >= NNODES
#define CSR_CAP (NEDGES + 4 * NNODES)
typedef unsigned long long ull;

// ---------------- device scratch (static, zero-init at load) ----------------
__device__ int   g_degs[NNODES];   // src-degree (re-zeroed by final combine)
__device__ int   g_cnt[NNODES];    // dst-degree
__device__ int   g_cur[NNODES];    // scatter cursors
__device__ int   g_off[NNODES];    // padded CSR segment starts
__device__ int   g_total;          // atomic base for scan
__device__ float g_dinv[NNODES];
__device__ ull   g_csr[CSR_CAP];   // src[0:32) | fp32 w [32:64); pads re-zeroed per call
__device__ float g_A[NNODES * HIDF];
__device__ float g_B[NNODES * HIDF];
__device__ float g_C[NNODES * HIDF];
__device__ float g_D[NNODES * HIDF];

// ---------------- f32x2 helpers ----------------
__device__ __forceinline__ ull packf2(float x, float y) {
    ull r; asm("mov.b64 %0, {%1, %2};" : "=l"(r) : "f"(x), "f"(y)); return r;
}
__device__ __forceinline__ void unpackf2(ull v, float& x, float& y) {
    asm("mov.b64 {%0, %1}, %2;" : "=f"(x), "=f"(y) : "l"(v));
}
__device__ __forceinline__ void fmaf2(ull& a, ull b, ull c) {
    asm("fma.rn.f32x2 %0, %1, %2, %0;" : "+l"(a) : "l"(b), "l"(c));
}
__device__ __forceinline__ void fmaf2v(ull& a, ull w, float x, float y) {
    ull v; asm("mov.b64 %0, {%1, %2};" : "=l"(v) : "f"(x), "f"(y));
    asm("fma.rn.f32x2 %0, %1, %2, %0;" : "+l"(a) : "l"(w), "l"(v));
}

// probe: int32 data read as int64 -> lo + hi*2^32, out of [0,N) w.h.p.
__device__ __forceinline__ bool probe64(const void* ei) {
    const long long* p = (const long long*)ei;
    bool ok = true;
    for (int j = 0; j < 64; j++) { long long v = p[j]; ok &= (v >= 0 && v < NNODES); }
    return ok;
}

// L1: degree histograms
__global__ void k_hist(const void* __restrict__ ei) {
    __shared__ int s64;
    if (threadIdx.x == 0) s64 = probe64(ei) ? 1 : 0;
    __syncthreads();
    int e = blockIdx.x * blockDim.x + threadIdx.x;
    if (e < NEDGES) {
        int s, d;
        if (s64) {
            s = (int)reinterpret_cast<const long long*>(ei)[e];
            d = (int)reinterpret_cast<const long long*>(ei)[NEDGES + e];
        } else {
            s = reinterpret_cast<const int*>(ei)[e];
            d = reinterpret_cast<const int*>(ei)[NEDGES + e];
        }
        s = min(max(s, 0), NNODES - 1);
        d = min(max(d, 0), NNODES - 1);
        atomicAdd(&g_degs[s], 1);
        atomicAdd(&g_cnt[d], 1);
    }
}

// L2: single-pass scan over PADDED counts + dinv + ZERO the pad slots.
// (Atomic block base -> segment placement varies per call; pads must be
//  re-zeroed every call or stale edge records from prior calls leak in.)
__global__ __launch_bounds__(SCAN_BS) void k_scan() {
    __shared__ int s[SCAN_BS];
    __shared__ int sbase;
    int tid = threadIdx.x;
    int i = blockIdx.x * SCAN_BS + tid;
    int c = (i < NNODES) ? g_cnt[i] : 0;
    int v = (c + 3) & ~3;
    s[tid] = v;
    if (i < NNODES) {
        float dg = (float)g_degs[i];
        g_dinv[i] = (dg > 0.f) ? rsqrtf(dg) : 0.f;
    }
    __syncthreads();
    for (int d = 1; d < SCAN_BS; d <<= 1) {
        int t = (tid >= d) ? s[tid - d] : 0;
        __syncthreads();
        s[tid] += t;
        __syncthreads();
    }
    if (tid == SCAN_BS - 1) sbase = atomicAdd(&g_total, s[tid]);
    __syncthreads();
    if (i < NNODES) {
        int off = sbase + s[tid] - v;
        g_off[i] = off;
        for (int j = c; j < v; j++) g_csr[off + j] = 0ULL;   // zero pads
    }
}

// L3 (fused): blocks [0,12500) scatter edges; blocks [12500,37500) mlp0 -> A
#define SCAT_BLKS 12500
__global__ __launch_bounds__(256) void k_scatter_mlp0(const void* __restrict__ ei,
                                                      const float* __restrict__ x,
                                                      const float* __restrict__ W0,
                                                      const float* __restrict__ b0) {
    if (blockIdx.x < SCAT_BLKS) {
        __shared__ int s64;
        if (threadIdx.x == 0) s64 = probe64(ei) ? 1 : 0;
        __syncthreads();
        int e = blockIdx.x * 256 + threadIdx.x;
        if (e < NEDGES) {
            int s, d;
            if (s64) {
                s = (int)reinterpret_cast<const long long*>(ei)[e];
                d = (int)reinterpret_cast<const long long*>(ei)[NEDGES + e];
            } else {
                s = reinterpret_cast<const int*>(ei)[e];
                d = reinterpret_cast<const int*>(ei)[NEDGES + e];
            }
            s = min(max(s, 0), NNODES - 1);
            d = min(max(d, 0), NNODES - 1);
            unsigned wb = __float_as_uint(-g_dinv[s] * g_dinv[d]);
            int pos = g_off[d] + atomicAdd(&g_cur[d], 1);
            g_csr[pos] = (ull)(unsigned)s | ((ull)wb << 32);
        }
    } else {
        __shared__ float sW[96];
        __shared__ float sb[32];
        int tid = threadIdx.x;
        if (tid < 96) sW[tid] = W0[tid];
        if (tid < 32) sb[tid] = b0[tid];
        __syncthreads();
        int node = (blockIdx.x - SCAT_BLKS) * 8 + (tid >> 5);
        int o = tid & 31;
        if (node < NNODES) {
            float x0 = x[node * 3 + 0];
            float x1 = x[node * 3 + 1];
            float x2 = x[node * 3 + 2];
            float a = sb[o] + x0 * sW[o] + x1 * sW[32 + o] + x2 * sW[64 + o];
            g_A[node * HIDF + o] = fmaxf(a, 0.f);
        }
    }
}

// Prop: 1 node/warp, 4 edge-slots x 8 feature-lanes. Each gather LDG.128
// covers one 16B chunk; 8 lanes of an edge-slot hit ONE 128B line ->
// 1 L1 wavefront per edge (wavefront-optimal). CSR load = 8-lane broadcast.
__global__ __launch_bounds__(256) void k_prop(const float* __restrict__ x,
                                              float* __restrict__ y) {
    int node = (blockIdx.x * 256 + threadIdx.x) >> 5;
    int lane = threadIdx.x & 31;
    int es = lane >> 3;         // edge slot 0..3
    int fg = lane & 7;          // 16B feature chunk 0..7
    int beg = __ldg(&g_off[node]);
    int deg = __ldg(&g_cnt[node]);
    int end = beg + ((deg + 3) & ~3);

    ull a0 = 0, a1 = 0;
#pragma unroll 2
    for (int i = beg + es; i < end; i += 4) {
        ull p = __ldg(&g_csr[i]);
        float w = __uint_as_float((unsigned)(p >> 32));
        int s = (int)(unsigned)p;
        float4 v = __ldg(reinterpret_cast<const float4*>(x + s * HIDF) + fg);
        ull wp = packf2(w, w);
        fmaf2v(a0, wp, v.x, v.y);
        fmaf2v(a1, wp, v.z, v.w);
    }

    float f0, f1, f2, f3;
    unpackf2(a0, f0, f1); unpackf2(a1, f2, f3);

    const unsigned FULL = 0xffffffffu;
#pragma unroll
    for (int d = 8; d <= 16; d <<= 1) {
        f0 += __shfl_xor_sync(FULL, f0, d);
        f1 += __shfl_xor_sync(FULL, f1, d);
        f2 += __shfl_xor_sync(FULL, f2, d);
        f3 += __shfl_xor_sync(FULL, f3, d);
    }
    if (es == 0) {
        *reinterpret_cast<float4*>(y + node * HIDF + fg * 4) =
            make_float4(f0, f1, f2, f3);
    }
}

// Combine: 64 nodes/block, thread = 2 nodes x 4 outs, fma.rn.f32x2 mainloop.
// FINAL also computes head dot-product and re-zeroes histogram arrays.
template <bool RESID, bool FINAL>
__global__ __launch_bounds__(256) void k_combine(const float* __restrict__ T0,
                                                 const float* __restrict__ T1,
                                                 const float* __restrict__ P2,
                                                 const float* __restrict__ W,
                                                 const float* __restrict__ bias,
                                                 const float* __restrict__ resid,
                                                 float* __restrict__ out,
                                                 const float* __restrict__ W1,
                                                 const float* __restrict__ b1) {
    __shared__ __align__(16) float sW[3 * 32 * 32];   // 12 KB
    __shared__ __align__(16) float sT[64 * 100];      // 25.6 KB
    __shared__ __align__(16) float sb[32];
    __shared__ __align__(16) float sW1[32];

    int tid = threadIdx.x;
    if (FINAL) {                       // fused cleanup for next replay
        int gt = blockIdx.x * 256 + tid;
        if (gt < NNODES) { g_degs[gt] = 0; g_cnt[gt] = 0; g_cur[gt] = 0; }
        if (gt == 0) g_total = 0;
    }
    for (int i = tid; i < 3072; i += 256) sW[i] = W[i];
    if (tid < 32) {
        sb[tid] = bias[tid];
        if (FINAL) sW1[tid] = W1[tid];
    }
    int nodeBase = blockIdx.x * 64;
    {
        int node = tid >> 2;           // 0..63
        int part = tid & 3;            // floats part*8 .. +7
        int gidx = (nodeBase + node) * HIDF + part * 8;
        float4 u00 = *reinterpret_cast<const float4*>(T0 + gidx);
        float4 u01 = *reinterpret_cast<const float4*>(T0 + gidx + 4);
        float4 u10 = *reinterpret_cast<const float4*>(T1 + gidx);
        float4 u11 = *reinterpret_cast<const float4*>(T1 + gidx + 4);
        float4 u20 = *reinterpret_cast<const float4*>(P2 + gidx);
        float4 u21 = *reinterpret_cast<const float4*>(P2 + gidx + 4);
        float* st = &sT[node * 100 + part * 8];
        st[0] = u00.x; st[1] = u00.y; st[2] = u00.z; st[3] = u00.w;
        st[4] = u01.x; st[5] = u01.y; st[6] = u01.z; st[7] = u01.w;
        st[32] = u10.x; st[33] = u10.y; st[34] = u10.z; st[35] = u10.w;
        st[36] = u11.x; st[37] = u11.y; st[38] = u11.z; st[39] = u11.w;
        st[64] = 2.f * u20.x - u00.x; st[65] = 2.f * u20.y - u00.y;
        st[66] = 2.f * u20.z - u00.z; st[67] = 2.f * u20.w - u00.w;
        st[68] = 2.f * u21.x - u01.x; st[69] = 2.f * u21.y - u01.y;
        st[70] = 2.f * u21.z - u01.z; st[71] = 2.f * u21.w - u01.w;
    }
    __syncthreads();

    int ng = tid >> 3;                 // 0..31
    int og = (tid & 7) * 4;
    int n0 = ng * 2, n1 = n0 + 1;

    double2 bv = *reinterpret_cast<const double2*>(sb + og);
    ull a00 = __double_as_longlong(bv.x);
    ull a01 = __double_as_longlong(bv.y);
    ull a10 = a00, a11 = a01;

    const float* t0p = &sT[n0 * 100];
    const float* t1p = &sT[n1 * 100];
#pragma unroll 8
    for (int k = 0; k < 96; k++) {
        float t0 = t0p[k];
        float t1 = t1p[k];
        ull tp0 = packf2(t0, t0);
        ull tp1 = packf2(t1, t1);
        double2 wv = *reinterpret_cast<const double2*>(sW + k * 32 + og);
        ull w01 = __double_as_longlong(wv.x);
        ull w23 = __double_as_longlong(wv.y);
        fmaf2(a00, tp0, w01);
        fmaf2(a01, tp0, w23);
        fmaf2(a10, tp1, w01);
        fmaf2(a11, tp1, w23);
    }

    float f0, f1, f2, f3, f4, f5, f6, f7;
    unpackf2(a00, f0, f1); unpackf2(a01, f2, f3);
    unpackf2(a10, f4, f5); unpackf2(a11, f6, f7);

    int gi0 = (nodeBase + n0) * HIDF + og;
    int gi1 = (nodeBase + n1) * HIDF + og;
    if (RESID) {
        float4 r0 = *reinterpret_cast<const float4*>(resid + gi0);
        float4 r1 = *reinterpret_cast<const float4*>(resid + gi1);
        f0 += r0.x; f1 += r0.y; f2 += r0.z; f3 += r0.w;
        f4 += r1.x; f5 += r1.y; f6 += r1.z; f7 += r1.w;
    }
    f0 = fmaxf(f0, 0.f); f1 = fmaxf(f1, 0.f); f2 = fmaxf(f2, 0.f); f3 = fmaxf(f3, 0.f);
    f4 = fmaxf(f4, 0.f); f5 = fmaxf(f5, 0.f); f6 = fmaxf(f6, 0.f); f7 = fmaxf(f7, 0.f);

    if (!FINAL) {
        *reinterpret_cast<float4*>(out + gi0) = make_float4(f0, f1, f2, f3);
        *reinterpret_cast<float4*>(out + gi1) = make_float4(f4, f5, f6, f7);
    } else {
        float p0 = f0 * sW1[og] + f1 * sW1[og + 1] + f2 * sW1[og + 2] + f3 * sW1[og + 3];
        float p1 = f4 * sW1[og] + f5 * sW1[og + 1] + f6 * sW1[og + 2] + f7 * sW1[og + 3];
        const unsigned FULL = 0xffffffffu;
        p0 += __shfl_xor_sync(FULL, p0, 1);
        p1 += __shfl_xor_sync(FULL, p1, 1);
        p0 += __shfl_xor_sync(FULL, p0, 2);
        p1 += __shfl_xor_sync(FULL, p1, 2);
        p0 += __shfl_xor_sync(FULL, p0, 4);
        p1 += __shfl_xor_sync(FULL, p1, 4);
        if ((tid & 7) == 0) {
            float bb = b1[0];
            out[nodeBase + n0] = p0 + bb;
            out[nodeBase + n1] = p1 + bb;
        }
    }
}

// ---------------- host ----------------
extern "C" void kernel_launch(void* const* d_in, const int* in_sizes, int n_in,
                              void* d_out, int out_size) {
    const float* x    = (const float*)d_in[0];
    const void*  ei   = d_in[1];
    const float* W0   = (const float*)d_in[2];
    const float* b0   = (const float*)d_in[3];
    const float* c11W = (const float*)d_in[4];
    const float* c11b = (const float*)d_in[5];
    const float* c12W = (const float*)d_in[6];
    const float* c12b = (const float*)d_in[7];
    const float* c21W = (const float*)d_in[8];
    const float* c21b = (const float*)d_in[9];
    const float* c22W = (const float*)d_in[10];
    const float* c22b = (const float*)d_in[11];
    const float* W1   = (const float*)d_in[12];
    const float* b1   = (const float*)d_in[13];
    float*       out  = (float*)d_out;

    float *A, *B, *C, *D;
    cudaGetSymbolAddress((void**)&A, g_A);
    cudaGetSymbolAddress((void**)&B, g_B);
    cudaGetSymbolAddress((void**)&C, g_C);
    cudaGetSymbolAddress((void**)&D, g_D);

    const int TB = 256;
    const int gb_edges = (NEDGES + TB - 1) / TB;   // 12500
    const int gb_prop  = NNODES * 32 / TB;         // 25000 exact (1 node/warp)
    const int gb_comb  = NNODES / 64;              // 3125 exact

    // setup: 3 launches -> first prop is launch #4 (the profiled slot)
    k_hist<<<gb_edges, TB>>>(ei);
    k_scan<<<NBLK_SCAN, SCAN_BS>>>();
    k_scatter_mlp0<<<SCAT_BLKS + 25000, TB>>>(ei, x, W0, b0);

    // ---- block 1, conv 1: D = relu(cheb(A)) ----
    k_prop<<<gb_prop, TB>>>(A, B);
    k_prop<<<gb_prop, TB>>>(B, C);
    k_combine<false, false><<<gb_comb, TB>>>(A, B, C, c11W, c11b, nullptr, D, nullptr, nullptr);

    // ---- block 1, conv 2: A = relu(cheb(D) + A) ----
    k_prop<<<gb_prop, TB>>>(D, B);
    k_prop<<<gb_prop, TB>>>(B, C);
    k_combine<true, false><<<gb_comb, TB>>>(D, B, C, c12W, c12b, A, A, nullptr, nullptr);

    // ---- block 2, conv 1: D = relu(cheb(A)) ----
    k_prop<<<gb_prop, TB>>>(A, B);
    k_prop<<<gb_prop, TB>>>(B, C);
    k_combine<false, false><<<gb_comb, TB>>>(A, B, C, c21W, c21b, nullptr, D, nullptr, nullptr);

    // ---- block 2, conv 2 + head (+ fused cleanup) ----
    k_prop<<<gb_prop, TB>>>(D, B);
    k_prop<<<gb_prop, TB>>>(B, C);
    k_combine<true, true><<<gb_comb, TB>>>(D, B, C, c22W, c22b, A, out, W1, b1);
}

// round 11
// speedup vs baseline: 1.1820x; 1.1820x over previous
#include <cuda_runtime.h>

#define NNODES 200000
#define NEDGES 3200000
#define HIDF 32
#define SCAN_BS 1024
#define NBLK_SCAN 196           // 196*1024 >= NNODES
#define CSR_CAP (NEDGES + 4 * NNODES)
typedef unsigned long long ull;

// ---------------- device scratch (static, zero-init at load) ----------------
__device__ int   g_degs[NNODES];   // src-degree (re-zeroed by final combine)
__device__ int   g_cnt[NNODES];    // dst-degree
__device__ int   g_cur[NNODES];    // scatter cursors
__device__ int   g_off[NNODES];    // padded CSR segment starts
__device__ int   g_total;          // atomic base for scan
__device__ float g_dinv[NNODES];
__device__ ull   g_csr[CSR_CAP];   // src[0:32) | fp32 w [32:64); pads re-zeroed per call
__device__ float g_A[NNODES * HIDF];
__device__ float g_B[NNODES * HIDF];
__device__ float g_C[NNODES * HIDF];
__device__ float g_D[NNODES * HIDF];

// ---------------- f32x2 helpers ----------------
__device__ __forceinline__ ull packf2(float x, float y) {
    ull r; asm("mov.b64 %0, {%1, %2};" : "=l"(r) : "f"(x), "f"(y)); return r;
}
__device__ __forceinline__ void unpackf2(ull v, float& x, float& y) {
    asm("mov.b64 {%0, %1}, %2;" : "=f"(x), "=f"(y) : "l"(v));
}
__device__ __forceinline__ void fmaf2(ull& a, ull b, ull c) {
    asm("fma.rn.f32x2 %0, %1, %2, %0;" : "+l"(a) : "l"(b), "l"(c));
}
__device__ __forceinline__ void fmaf2v(ull& a, ull w, float x, float y) {
    ull v; asm("mov.b64 %0, {%1, %2};" : "=l"(v) : "f"(x), "f"(y));
    asm("fma.rn.f32x2 %0, %1, %2, %0;" : "+l"(a) : "l"(w), "l"(v));
}

// probe: int32 data read as int64 -> lo + hi*2^32, out of [0,N) w.h.p.
__device__ __forceinline__ bool probe64(const void* ei) {
    const long long* p = (const long long*)ei;
    bool ok = true;
    for (int j = 0; j < 64; j++) { long long v = p[j]; ok &= (v >= 0 && v < NNODES); }
    return ok;
}

// L1: degree histograms
__global__ void k_hist(const void* __restrict__ ei) {
    __shared__ int s64;
    if (threadIdx.x == 0) s64 = probe64(ei) ? 1 : 0;
    __syncthreads();
    int e = blockIdx.x * blockDim.x + threadIdx.x;
    if (e < NEDGES) {
        int s, d;
        if (s64) {
            s = (int)reinterpret_cast<const long long*>(ei)[e];
            d = (int)reinterpret_cast<const long long*>(ei)[NEDGES + e];
        } else {
            s = reinterpret_cast<const int*>(ei)[e];
            d = reinterpret_cast<const int*>(ei)[NEDGES + e];
        }
        s = min(max(s, 0), NNODES - 1);
        d = min(max(d, 0), NNODES - 1);
        atomicAdd(&g_degs[s], 1);
        atomicAdd(&g_cnt[d], 1);
    }
}

// L2: single-pass scan over PADDED counts + dinv + ZERO the pad slots.
// (Atomic block base -> segment placement varies per call; pads must be
//  re-zeroed every call or stale edge records from prior calls leak in.)
__global__ __launch_bounds__(SCAN_BS) void k_scan() {
    __shared__ int s[SCAN_BS];
    __shared__ int sbase;
    int tid = threadIdx.x;
    int i = blockIdx.x * SCAN_BS + tid;
    int c = (i < NNODES) ? g_cnt[i] : 0;
    int v = (c + 3) & ~3;
    s[tid] = v;
    if (i < NNODES) {
        float dg = (float)g_degs[i];
        g_dinv[i] = (dg > 0.f) ? rsqrtf(dg) : 0.f;
    }
    __syncthreads();
    for (int d = 1; d < SCAN_BS; d <<= 1) {
        int t = (tid >= d) ? s[tid - d] : 0;
        __syncthreads();
        s[tid] += t;
        __syncthreads();
    }
    if (tid == SCAN_BS - 1) sbase = atomicAdd(&g_total, s[tid]);
    __syncthreads();
    if (i < NNODES) {
        int off = sbase + s[tid] - v;
        g_off[i] = off;
        for (int j = c; j < v; j++) g_csr[off + j] = 0ULL;   // zero pads
    }
}

// L3 (fused): blocks [0,12500) scatter edges; blocks [12500,37500) mlp0 -> A
#define SCAT_BLKS 12500
__global__ __launch_bounds__(256) void k_scatter_mlp0(const void* __restrict__ ei,
                                                      const float* __restrict__ x,
                                                      const float* __restrict__ W0,
                                                      const float* __restrict__ b0) {
    if (blockIdx.x < SCAT_BLKS) {
        __shared__ int s64;
        if (threadIdx.x == 0) s64 = probe64(ei) ? 1 : 0;
        __syncthreads();
        int e = blockIdx.x * 256 + threadIdx.x;
        if (e < NEDGES) {
            int s, d;
            if (s64) {
                s = (int)reinterpret_cast<const long long*>(ei)[e];
                d = (int)reinterpret_cast<const long long*>(ei)[NEDGES + e];
            } else {
                s = reinterpret_cast<const int*>(ei)[e];
                d = reinterpret_cast<const int*>(ei)[NEDGES + e];
            }
            s = min(max(s, 0), NNODES - 1);
            d = min(max(d, 0), NNODES - 1);
            unsigned wb = __float_as_uint(-g_dinv[s] * g_dinv[d]);
            int pos = g_off[d] + atomicAdd(&g_cur[d], 1);
            g_csr[pos] = (ull)(unsigned)s | ((ull)wb << 32);
        }
    } else {
        __shared__ float sW[96];
        __shared__ float sb[32];
        int tid = threadIdx.x;
        if (tid < 96) sW[tid] = W0[tid];
        if (tid < 32) sb[tid] = b0[tid];
        __syncthreads();
        int node = (blockIdx.x - SCAT_BLKS) * 8 + (tid >> 5);
        int o = tid & 31;
        if (node < NNODES) {
            float x0 = x[node * 3 + 0];
            float x1 = x[node * 3 + 1];
            float x2 = x[node * 3 + 2];
            float a = sb[o] + x0 * sW[o] + x1 * sW[32 + o] + x2 * sW[64 + o];
            g_A[node * HIDF + o] = fmaxf(a, 0.f);
        }
    }
}

// Prop: 2 nodes/warp, lanes = 2 nodes x 2 pair-slots x 8 feature-lanes.
// Each lane: one LDG.128 of TWO csr records + two full-row gathers (LDG.128,
// 8 lanes cover one 128B row -> 1 L1 wavefront per edge). 8 edges in flight
// per warp-iter (R9's MLP) at R10's wavefront cost. Pads are (0, w=0).
__global__ __launch_bounds__(256) void k_prop(const float* __restrict__ x,
                                              float* __restrict__ y) {
    int warpId = (blockIdx.x * 256 + threadIdx.x) >> 5;
    int lane = threadIdx.x & 31;
    int nd = lane >> 4;            // node within warp
    int es = (lane >> 3) & 1;      // record-pair slot
    int fg = lane & 7;             // 16B feature chunk
    int node = warpId * 2 + nd;
    int beg = __ldg(&g_off[node]);
    int deg = __ldg(&g_cnt[node]);
    int end = beg + ((deg + 3) & ~3);

    ull a0 = 0, a1 = 0;
#pragma unroll 2
    for (int i = beg + 2 * es; i < end; i += 4) {
        ulonglong2 pr = __ldg(reinterpret_cast<const ulonglong2*>(&g_csr[i]));
        int   sa = (int)(unsigned)pr.x;
        float wa = __uint_as_float((unsigned)(pr.x >> 32));
        int   sb = (int)(unsigned)pr.y;
        float wb = __uint_as_float((unsigned)(pr.y >> 32));
        float4 va = __ldg(reinterpret_cast<const float4*>(x + sa * HIDF) + fg);
        float4 vb = __ldg(reinterpret_cast<const float4*>(x + sb * HIDF) + fg);
        ull wpa = packf2(wa, wa);
        ull wpb = packf2(wb, wb);
        fmaf2v(a0, wpa, va.x, va.y);
        fmaf2v(a1, wpa, va.z, va.w);
        fmaf2v(a0, wpb, vb.x, vb.y);
        fmaf2v(a1, wpb, vb.z, vb.w);
    }

    float f0, f1, f2, f3;
    unpackf2(a0, f0, f1); unpackf2(a1, f2, f3);

    const unsigned FULL = 0xffffffffu;
    f0 += __shfl_xor_sync(FULL, f0, 8);
    f1 += __shfl_xor_sync(FULL, f1, 8);
    f2 += __shfl_xor_sync(FULL, f2, 8);
    f3 += __shfl_xor_sync(FULL, f3, 8);

    if (es == 0) {
        *reinterpret_cast<float4*>(y + node * HIDF + fg * 4) =
            make_float4(f0, f1, f2, f3);
    }
}

// Combine: 64 nodes/block, thread = 2 nodes x 4 outs, fma.rn.f32x2 mainloop.
// FINAL also computes head dot-product and re-zeroes histogram arrays.
template <bool RESID, bool FINAL>
__global__ __launch_bounds__(256) void k_combine(const float* __restrict__ T0,
                                                 const float* __restrict__ T1,
                                                 const float* __restrict__ P2,
                                                 const float* __restrict__ W,
                                                 const float* __restrict__ bias,
                                                 const float* __restrict__ resid,
                                                 float* __restrict__ out,
                                                 const float* __restrict__ W1,
                                                 const float* __restrict__ b1) {
    __shared__ __align__(16) float sW[3 * 32 * 32];   // 12 KB
    __shared__ __align__(16) float sT[64 * 100];      // 25.6 KB
    __shared__ __align__(16) float sb[32];
    __shared__ __align__(16) float sW1[32];

    int tid = threadIdx.x;
    if (FINAL) {                       // fused cleanup for next replay
        int gt = blockIdx.x * 256 + tid;
        if (gt < NNODES) { g_degs[gt] = 0; g_cnt[gt] = 0; g_cur[gt] = 0; }
        if (gt == 0) g_total = 0;
    }
    for (int i = tid; i < 3072; i += 256) sW[i] = W[i];
    if (tid < 32) {
        sb[tid] = bias[tid];
        if (FINAL) sW1[tid] = W1[tid];
    }
    int nodeBase = blockIdx.x * 64;
    {
        int node = tid >> 2;           // 0..63
        int part = tid & 3;            // floats part*8 .. +7
        int gidx = (nodeBase + node) * HIDF + part * 8;
        float4 u00 = *reinterpret_cast<const float4*>(T0 + gidx);
        float4 u01 = *reinterpret_cast<const float4*>(T0 + gidx + 4);
        float4 u10 = *reinterpret_cast<const float4*>(T1 + gidx);
        float4 u11 = *reinterpret_cast<const float4*>(T1 + gidx + 4);
        float4 u20 = *reinterpret_cast<const float4*>(P2 + gidx);
        float4 u21 = *reinterpret_cast<const float4*>(P2 + gidx + 4);
        float* st = &sT[node * 100 + part * 8];
        st[0] = u00.x; st[1] = u00.y; st[2] = u00.z; st[3] = u00.w;
        st[4] = u01.x; st[5] = u01.y; st[6] = u01.z; st[7] = u01.w;
        st[32] = u10.x; st[33] = u10.y; st[34] = u10.z; st[35] = u10.w;
        st[36] = u11.x; st[37] = u11.y; st[38] = u11.z; st[39] = u11.w;
        st[64] = 2.f * u20.x - u00.x; st[65] = 2.f * u20.y - u00.y;
        st[66] = 2.f * u20.z - u00.z; st[67] = 2.f * u20.w - u00.w;
        st[68] = 2.f * u21.x - u01.x; st[69] = 2.f * u21.y - u01.y;
        st[70] = 2.f * u21.z - u01.z; st[71] = 2.f * u21.w - u01.w;
    }
    __syncthreads();

    int ng = tid >> 3;                 // 0..31
    int og = (tid & 7) * 4;
    int n0 = ng * 2, n1 = n0 + 1;

    double2 bv = *reinterpret_cast<const double2*>(sb + og);
    ull a00 = __double_as_longlong(bv.x);
    ull a01 = __double_as_longlong(bv.y);
    ull a10 = a00, a11 = a01;

    const float* t0p = &sT[n0 * 100];
    const float* t1p = &sT[n1 * 100];
#pragma unroll 8
    for (int k = 0; k < 96; k++) {
        float t0 = t0p[k];
        float t1 = t1p[k];
        ull tp0 = packf2(t0, t0);
        ull tp1 = packf2(t1, t1);
        double2 wv = *reinterpret_cast<const double2*>(sW + k * 32 + og);
        ull w01 = __double_as_longlong(wv.x);
        ull w23 = __double_as_longlong(wv.y);
        fmaf2(a00, tp0, w01);
        fmaf2(a01, tp0, w23);
        fmaf2(a10, tp1, w01);
        fmaf2(a11, tp1, w23);
    }

    float f0, f1, f2, f3, f4, f5, f6, f7;
    unpackf2(a00, f0, f1); unpackf2(a01, f2, f3);
    unpackf2(a10, f4, f5); unpackf2(a11, f6, f7);

    int gi0 = (nodeBase + n0) * HIDF + og;
    int gi1 = (nodeBase + n1) * HIDF + og;
    if (RESID) {
        float4 r0 = *reinterpret_cast<const float4*>(resid + gi0);
        float4 r1 = *reinterpret_cast<const float4*>(resid + gi1);
        f0 += r0.x; f1 += r0.y; f2 += r0.z; f3 += r0.w;
        f4 += r1.x; f5 += r1.y; f6 += r1.z; f7 += r1.w;
    }
    f0 = fmaxf(f0, 0.f); f1 = fmaxf(f1, 0.f); f2 = fmaxf(f2, 0.f); f3 = fmaxf(f3, 0.f);
    f4 = fmaxf(f4, 0.f); f5 = fmaxf(f5, 0.f); f6 = fmaxf(f6, 0.f); f7 = fmaxf(f7, 0.f);

    if (!FINAL) {
        *reinterpret_cast<float4*>(out + gi0) = make_float4(f0, f1, f2, f3);
        *reinterpret_cast<float4*>(out + gi1) = make_float4(f4, f5, f6, f7);
    } else {
        float p0 = f0 * sW1[og] + f1 * sW1[og + 1] + f2 * sW1[og + 2] + f3 * sW1[og + 3];
        float p1 = f4 * sW1[og] + f5 * sW1[og + 1] + f6 * sW1[og + 2] + f7 * sW1[og + 3];
        const unsigned FULL = 0xffffffffu;
        p0 += __shfl_xor_sync(FULL, p0, 1);
        p1 += __shfl_xor_sync(FULL, p1, 1);
        p0 += __shfl_xor_sync(FULL, p0, 2);
        p1 += __shfl_xor_sync(FULL, p1, 2);
        p0 += __shfl_xor_sync(FULL, p0, 4);
        p1 += __shfl_xor_sync(FULL, p1, 4);
        if ((tid & 7) == 0) {
            float bb = b1[0];
            out[nodeBase + n0] = p0 + bb;
            out[nodeBase + n1] = p1 + bb;
        }
    }
}

// ---------------- host ----------------
extern "C" void kernel_launch(void* const* d_in, const int* in_sizes, int n_in,
                              void* d_out, int out_size) {
    const float* x    = (const float*)d_in[0];
    const void*  ei   = d_in[1];
    const float* W0   = (const float*)d_in[2];
    const float* b0   = (const float*)d_in[3];
    const float* c11W = (const float*)d_in[4];
    const float* c11b = (const float*)d_in[5];
    const float* c12W = (const float*)d_in[6];
    const float* c12b = (const float*)d_in[7];
    const float* c21W = (const float*)d_in[8];
    const float* c21b = (const float*)d_in[9];
    const float* c22W = (const float*)d_in[10];
    const float* c22b = (const float*)d_in[11];
    const float* W1   = (const float*)d_in[12];
    const float* b1   = (const float*)d_in[13];
    float*       out  = (float*)d_out;

    float *A, *B, *C, *D;
    cudaGetSymbolAddress((void**)&A, g_A);
    cudaGetSymbolAddress((void**)&B, g_B);
    cudaGetSymbolAddress((void**)&C, g_C);
    cudaGetSymbolAddress((void**)&D, g_D);

    const int TB = 256;
    const int gb_edges = (NEDGES + TB - 1) / TB;   // 12500
    const int gb_prop  = (NNODES / 2) * 32 / TB;   // 12500 exact (2 nodes/warp)
    const int gb_comb  = NNODES / 64;              // 3125 exact

    // setup: 3 launches -> first prop is launch #4 (the profiled slot)
    k_hist<<<gb_edges, TB>>>(ei);
    k_scan<<<NBLK_SCAN, SCAN_BS>>>();
    k_scatter_mlp0<<<SCAT_BLKS + 25000, TB>>>(ei, x, W0, b0);

    // ---- block 1, conv 1: D = relu(cheb(A)) ----
    k_prop<<<gb_prop, TB>>>(A, B);
    k_prop<<<gb_prop, TB>>>(B, C);
    k_combine<false, false><<<gb_comb, TB>>>(A, B, C, c11W, c11b, nullptr, D, nullptr, nullptr);

    // ---- block 1, conv 2: A = relu(cheb(D) + A) ----
    k_prop<<<gb_prop, TB>>>(D, B);
    k_prop<<<gb_prop, TB>>>(B, C);
    k_combine<true, false><<<gb_comb, TB>>>(D, B, C, c12W, c12b, A, A, nullptr, nullptr);

    // ---- block 2, conv 1: D = relu(cheb(A)) ----
    k_prop<<<gb_prop, TB>>>(A, B);
    k_prop<<<gb_prop, TB>>>(B, C);
    k_combine<false, false><<<gb_comb, TB>>>(A, B, C, c21W, c21b, nullptr, D, nullptr, nullptr);

    // ---- block 2, conv 2 + head (+ fused cleanup) ----
    k_prop<<<gb_prop, TB>>>(D, B);
    k_prop<<<gb_prop, TB>>>(B, C);
    k_combine<true, true><<<gb_comb, TB>>>(D, B, C, c22W, c22b, A, out, W1, b1);
}